// round 3
// baseline (speedup 1.0000x reference)
#include <cuda_runtime.h>
#include <math.h>

#define D_MODEL 512
#define HEADS   8
#define HDIM    64
#define NSEQ    1024
#define TOPK    102
#define MAXM    2048   // B*N for B=2

// ---------------- scratch (static device globals; no allocs) ----------------
__device__ float g_QKV[3u * MAXM * D_MODEL];   // Q | K | V, each [M,512]
__device__ float g_att[MAXM * D_MODEL];        // attention output pre-Wo
__device__ unsigned char g_qh[MAXM * HEADS];   // [(b*8+h)*1024 + n]
__device__ unsigned char g_kh[MAXM * HEADS];

// ---------------- SGEMM: C = A[M,512] * W[512,512]^T, 32x64 tiles, 128 thr ----------------
#define BK 16
#define TBM 32
#define TBN 64

__device__ __forceinline__ void gemm_body(
    const float* __restrict__ A, const float* __restrict__ W,
    float* __restrict__ C, int bm, int bn)
{
    __shared__ __align__(16) float As[BK][TBM];
    __shared__ __align__(16) float Bs[BK][TBN];

    int tid  = threadIdx.x;
    int trow = tid >> 4;        // 0..7  -> rows trow*4
    int tcol = tid & 15;        // 0..15 -> cols tcol*4
    int arow = tid >> 2;        // 0..31
    int akc  = (tid & 3) << 2;  // 0,4,8,12
    int wrow = tid >> 1;        // 0..63
    int wkc  = (tid & 1) << 3;  // 0,8
    float acc[4][4] = {};

    for (int k0 = 0; k0 < D_MODEL; k0 += BK) {
        float4 av = *reinterpret_cast<const float4*>(&A[(size_t)(bm + arow) * D_MODEL + k0 + akc]);
        As[akc + 0][arow] = av.x; As[akc + 1][arow] = av.y;
        As[akc + 2][arow] = av.z; As[akc + 3][arow] = av.w;
#pragma unroll
        for (int p = 0; p < 2; ++p) {
            float4 wv = *reinterpret_cast<const float4*>(&W[(size_t)(bn + wrow) * D_MODEL + k0 + wkc + p * 4]);
            Bs[wkc + p * 4 + 0][wrow] = wv.x; Bs[wkc + p * 4 + 1][wrow] = wv.y;
            Bs[wkc + p * 4 + 2][wrow] = wv.z; Bs[wkc + p * 4 + 3][wrow] = wv.w;
        }
        __syncthreads();
#pragma unroll
        for (int k = 0; k < BK; ++k) {
            float4 a4 = *reinterpret_cast<const float4*>(&As[k][trow * 4]);
            float4 b4 = *reinterpret_cast<const float4*>(&Bs[k][tcol * 4]);
            float aR[4] = {a4.x, a4.y, a4.z, a4.w};
            float bR[4] = {b4.x, b4.y, b4.z, b4.w};
#pragma unroll
            for (int i = 0; i < 4; ++i)
#pragma unroll
                for (int j = 0; j < 4; ++j)
                    acc[i][j] = fmaf(aR[i], bR[j], acc[i][j]);
        }
        __syncthreads();
    }
#pragma unroll
    for (int i = 0; i < 4; ++i) {
        float4* dst = reinterpret_cast<float4*>(&C[(size_t)(bm + trow * 4 + i) * D_MODEL + bn + tcol * 4]);
        *dst = make_float4(acc[i][0], acc[i][1], acc[i][2], acc[i][3]);
    }
}

__global__ __launch_bounds__(128) void gemm_qkv_kernel(
    const float* __restrict__ A,
    const float* __restrict__ Wq, const float* __restrict__ Wk,
    const float* __restrict__ Wv, int M)
{
    int gn    = blockIdx.y * TBN;           // [0,1536)
    int which = gn >> 9;                    // 0:Q 1:K 2:V
    int bn    = gn & 511;
    const float* W = (which == 0) ? Wq : (which == 1) ? Wk : Wv;
    float* C = g_QKV + (size_t)which * M * D_MODEL;
    gemm_body(A, W, C, blockIdx.x * TBM, bn);
}

__global__ __launch_bounds__(128) void gemm_o_kernel(
    const float* __restrict__ Wo, float* __restrict__ Cout, int M)
{
    gemm_body(g_att, Wo, Cout, blockIdx.x * TBM, blockIdx.y * TBN);
}

// ---------------- LSH hashes ----------------
__global__ __launch_bounds__(256) void hash_kernel(const float* __restrict__ rv, int M)
{
    __shared__ float rs[HEADS * HDIM];
    for (int i = threadIdx.x; i < HEADS * HDIM; i += blockDim.x) rs[i] = rv[i];
    __syncthreads();

    int idx = blockIdx.x * blockDim.x + threadIdx.x;
    int total = 2 * M * HEADS;
    if (idx >= total) return;
    int isK = (idx >= M * HEADS) ? 1 : 0;
    int r = idx - isK * M * HEADS;
    int row = r >> 3;        // 0..M-1 (= b*1024+n)
    int h   = r & 7;

    const float4* src4 = reinterpret_cast<const float4*>(
        g_QKV + (size_t)isK * M * D_MODEL + (size_t)row * D_MODEL + h * HDIM);
    float dacc[8] = {};
#pragma unroll
    for (int c4 = 0; c4 < HDIM / 4; ++c4) {
        float4 xv = src4[c4];
#pragma unroll
        for (int k = 0; k < 8; ++k) {
            const float* rk = &rs[k * HDIM + c4 * 4];
            dacc[k] = fmaf(xv.x, rk[0], dacc[k]);
            dacc[k] = fmaf(xv.y, rk[1], dacc[k]);
            dacc[k] = fmaf(xv.z, rk[2], dacc[k]);
            dacc[k] = fmaf(xv.w, rk[3], dacc[k]);
        }
    }
    unsigned int bits = 0;
#pragma unroll
    for (int k = 0; k < 8; ++k) bits |= (dacc[k] >= 0.f ? 1u : 0u) << k;
    int bhn = ((row >> 10) * HEADS + h) * NSEQ + (row & (NSEQ - 1));
    (isK ? g_kh : g_qh)[bhn] = (unsigned char)bits;
}

// ---------------- sparse hyperbolic attention: one block per (b,h,n) ----------------
__global__ __launch_bounds__(128) void attn_kernel(int M)
{
    const int T = 128;
    const int PER = NSEQ / T;            // 8 contiguous j per thread
    int gid = blockIdx.x;                // bh*1024 + n
    int n  = gid & (NSEQ - 1);
    int bh = gid >> 10;
    int h = bh & 7, b = bh >> 3;

    const float* Q = g_QKV;
    const float* K = g_QKV + (size_t)M * D_MODEL;
    const float* V = g_QKV + 2 * (size_t)M * D_MODEL;

    __shared__ float qs[HDIM];
    __shared__ float sc[TOPK];
    __shared__ short selj[TOPK];
    __shared__ int hist[9];
    __shared__ int wsum_gt[4], wsum_eq[4];
    __shared__ int s_t, s_need;
    __shared__ float s_qn, s_mx, s_sum;
    __shared__ float red[4];
    __shared__ float obuf[HDIM];

    int tid = threadIdx.x, lane = tid & 31, warp = tid >> 5;
    size_t qoff = ((size_t)(b * NSEQ + n)) * D_MODEL + h * HDIM;
    if (tid < HDIM) qs[tid] = Q[qoff + tid];
    if (tid < 9) hist[tid] = 0;
    __syncthreads();

    // --- hash match counts for my 8 contiguous keys (register-resident) ---
    unsigned int qb = g_qh[bh * NSEQ + n];
    const unsigned char* khb = g_kh + bh * NSEQ;
    int base = tid * PER;
    uint2 kv8 = *reinterpret_cast<const uint2*>(khb + base);  // 8 bytes, aligned
    int m[PER];
#pragma unroll
    for (int i = 0; i < PER; ++i) {
        unsigned int byte = ((i < 4 ? kv8.x >> (8 * i) : kv8.y >> (8 * (i - 4))) & 0xFFu);
        m[i] = 8 - __popc(byte ^ qb);
    }

    // --- histogram: per-thread count per bucket, warp-reduce, 1 atomic/warp ---
#pragma unroll
    for (int v = 0; v < 9; ++v) {
        int c = 0;
#pragma unroll
        for (int i = 0; i < PER; ++i) c += (m[i] == v);
        c = __reduce_add_sync(0xffffffffu, c);
        if (lane == 0 && c) atomicAdd(&hist[v], c);
    }

    // q norm (warp 0)
    if (tid < 32) {
        float v = qs[tid] * qs[tid] + qs[tid + 32] * qs[tid + 32];
#pragma unroll
        for (int o = 16; o > 0; o >>= 1) v += __shfl_xor_sync(0xffffffffu, v, o);
        if (tid == 0) s_qn = v;
    }
    __syncthreads();

    if (tid == 0) {
        int cum = 0, t = 0, need = TOPK;
        for (int v = 8; v >= 0; --v) {
            if (cum + hist[v] >= TOPK) { t = v; need = TOPK - cum; break; }
            cum += hist[v];
        }
        s_t = t; s_need = need;
    }
    __syncthreads();
    int t = s_t, need = s_need, ngt = TOPK - need;

    // --- deterministic selection positions via two shuffle scans ---
    int cgt = 0, ceq = 0;
#pragma unroll
    for (int i = 0; i < PER; ++i) { cgt += (m[i] > t); ceq += (m[i] == t); }
    int sgt = cgt, seq = ceq;
#pragma unroll
    for (int o = 1; o < 32; o <<= 1) {
        int a = __shfl_up_sync(0xffffffffu, sgt, o); if (lane >= o) sgt += a;
        int e = __shfl_up_sync(0xffffffffu, seq, o); if (lane >= o) seq += e;
    }
    if (lane == 31) { wsum_gt[warp] = sgt; wsum_eq[warp] = seq; }
    __syncthreads();
    int rgt = sgt - cgt, req = seq - ceq;
#pragma unroll
    for (int w = 0; w < 4; ++w) {
        if (w < warp) { rgt += wsum_gt[w]; req += wsum_eq[w]; }
    }
#pragma unroll
    for (int i = 0; i < PER; ++i) {
        int j = base + i;
        if (m[i] > t) selj[rgt++] = (short)j;
        else if (m[i] == t) { if (req < need) selj[ngt + req] = (short)j; req++; }
    }
    __syncthreads();

    // --- Poincare distances for the selected keys ---
    float qn = s_qn;
    if (tid < TOPK) {
        int j = selj[tid];
        const float* kr = K + ((size_t)(b * NSEQ + j)) * D_MODEL + h * HDIM;
        float dsq = 0.f, kn = 0.f;
#pragma unroll
        for (int d0 = 0; d0 < HDIM; d0 += 4) {
            float4 kv = *reinterpret_cast<const float4*>(kr + d0);
            float dx = qs[d0 + 0] - kv.x, dy = qs[d0 + 1] - kv.y;
            float dz = qs[d0 + 2] - kv.z, dw = qs[d0 + 3] - kv.w;
            dsq += dx * dx + dy * dy + dz * dz + dw * dw;
            kn  += kv.x * kv.x + kv.y * kv.y + kv.z * kv.z + kv.w * kv.w;
        }
        float denom = fmaxf((1.f - qn) * (1.f - kn), 1e-6f);
        float ca = fmaxf(1.f + 2.f * dsq / denom, 1.f);
        sc[tid] = -acoshf(ca);
    }
    __syncthreads();

    // --- softmax over TOPK scores ---
    {
        float v = (tid < TOPK) ? sc[tid] : -3.4e38f;
#pragma unroll
        for (int o = 16; o > 0; o >>= 1) v = fmaxf(v, __shfl_xor_sync(0xffffffffu, v, o));
        if (lane == 0) red[warp] = v;
        __syncthreads();
        if (tid == 0) s_mx = fmaxf(fmaxf(red[0], red[1]), fmaxf(red[2], red[3]));
        __syncthreads();
        float e = (tid < TOPK) ? expf(sc[tid] - s_mx) : 0.f;
        if (tid < TOPK) sc[tid] = e;
        float sv = e;
#pragma unroll
        for (int o = 16; o > 0; o >>= 1) sv += __shfl_xor_sync(0xffffffffu, sv, o);
        if (lane == 0) red[warp] = sv;
        __syncthreads();
        if (tid == 0) s_sum = red[0] + red[1] + red[2] + red[3];
        __syncthreads();
    }
    float inv = 1.f / s_sum;

    // --- weighted V sum: two halves split the s-range, 16-wide prefetch ---
    int d = tid & (HDIM - 1);
    int half = tid >> 6;
    const float* Vb = V + (size_t)b * NSEQ * D_MODEL + h * HDIM + d;
    float acc = 0.f;
    int s0 = half * 51;
    int s1 = s0 + 51;
    for (int c = s0; c < s1; c += 16) {
        float w16[16];
        int   o16[16];
        float v16[16];
#pragma unroll
        for (int i = 0; i < 16; ++i) {
            int s = c + i;
            bool ok = (s < s1);
            int j = ok ? (int)selj[s] : 0;
            w16[i] = ok ? sc[s] : 0.f;
            o16[i] = j * D_MODEL;
        }
#pragma unroll
        for (int i = 0; i < 16; ++i) v16[i] = __ldg(Vb + o16[i]);
#pragma unroll
        for (int i = 0; i < 16; ++i) acc = fmaf(w16[i], v16[i], acc);
    }
    if (half == 0) obuf[d] = acc;
    __syncthreads();
    if (half == 1)
        g_att[((size_t)(b * NSEQ + n)) * D_MODEL + h * HDIM + d] = (obuf[d] + acc) * inv;
}

// ---------------- entry ----------------
extern "C" void kernel_launch(void* const* d_in, const int* in_sizes, int n_in,
                              void* d_out, int out_size)
{
    const float* x  = (const float*)d_in[0];
    const float* Wq = (const float*)d_in[1];
    const float* Wk = (const float*)d_in[2];
    const float* Wv = (const float*)d_in[3];
    const float* Wo = (const float*)d_in[4];
    const float* rv = (const float*)d_in[5];
    float* out = (float*)d_out;

    int M = in_sizes[0] / D_MODEL;   // B*N = 2048

    dim3 gq(M / TBM, (3 * D_MODEL) / TBN);    // (64, 24) = 1536 blocks
    gemm_qkv_kernel<<<gq, 128>>>(x, Wq, Wk, Wv, M);

    int hthreads = 2 * M * HEADS;             // 32768
    hash_kernel<<<(hthreads + 255) / 256, 256>>>(rv, M);

    attn_kernel<<<M * HEADS, 128>>>(M);       // 16384 blocks

    dim3 go(M / TBM, D_MODEL / TBN);          // (64, 8) = 512 blocks
    gemm_o_kernel<<<go, 128>>>(Wo, out, M);
}

// round 4
// speedup vs baseline: 1.1353x; 1.1353x over previous
#include <cuda_runtime.h>
#include <math.h>

#define D_MODEL 512
#define HEADS   8
#define HDIM    64
#define NSEQ    1024
#define TOPK    102
#define MAXM    2048   // B*N for B=2

// ---------------- scratch (static device globals; no allocs) ----------------
__device__ float g_QKV[3u * MAXM * D_MODEL];   // Q | K | V, each [M,512]
__device__ float g_att[MAXM * D_MODEL];        // attention output pre-Wo
__device__ float g_part[2u * MAXM * D_MODEL];  // split-K partials for Wo GEMM
__device__ unsigned char g_qh[MAXM * HEADS];   // [(b*8+h)*1024 + n]
__device__ unsigned char g_kh[MAXM * HEADS];
__device__ float g_qn[MAXM * HEADS];           // |q|^2 per (b,h,n)
__device__ float g_kn[MAXM * HEADS];           // |k|^2 per (b,h,n)

// ---------------- SGEMM: C = A[M,512] * W[512,512]^T, 32x64 tiles, 128 thr ----------------
#define BK 16
#define TBM 32
#define TBN 64

__device__ __forceinline__ void gemm_body(
    const float* __restrict__ A, const float* __restrict__ W,
    float* __restrict__ C, int bm, int bn, int kbeg, int kend)
{
    __shared__ __align__(16) float As[BK][TBM];
    __shared__ __align__(16) float Bs[BK][TBN];

    int tid  = threadIdx.x;
    int trow = tid >> 4;        // 0..7
    int tcol = tid & 15;        // 0..15
    int arow = tid >> 2;        // 0..31
    int akc  = (tid & 3) << 2;  // 0,4,8,12
    int wrow = tid >> 1;        // 0..63
    int wkc  = (tid & 1) << 3;  // 0,8
    float acc[4][4] = {};

    for (int k0 = kbeg; k0 < kend; k0 += BK) {
        float4 av = *reinterpret_cast<const float4*>(&A[(size_t)(bm + arow) * D_MODEL + k0 + akc]);
        As[akc + 0][arow] = av.x; As[akc + 1][arow] = av.y;
        As[akc + 2][arow] = av.z; As[akc + 3][arow] = av.w;
#pragma unroll
        for (int p = 0; p < 2; ++p) {
            float4 wv = *reinterpret_cast<const float4*>(&W[(size_t)(bn + wrow) * D_MODEL + k0 + wkc + p * 4]);
            Bs[wkc + p * 4 + 0][wrow] = wv.x; Bs[wkc + p * 4 + 1][wrow] = wv.y;
            Bs[wkc + p * 4 + 2][wrow] = wv.z; Bs[wkc + p * 4 + 3][wrow] = wv.w;
        }
        __syncthreads();
#pragma unroll
        for (int k = 0; k < BK; ++k) {
            float4 a4 = *reinterpret_cast<const float4*>(&As[k][trow * 4]);
            float4 b4 = *reinterpret_cast<const float4*>(&Bs[k][tcol * 4]);
            float aR[4] = {a4.x, a4.y, a4.z, a4.w};
            float bR[4] = {b4.x, b4.y, b4.z, b4.w};
#pragma unroll
            for (int i = 0; i < 4; ++i)
#pragma unroll
                for (int j = 0; j < 4; ++j)
                    acc[i][j] = fmaf(aR[i], bR[j], acc[i][j]);
        }
        __syncthreads();
    }
#pragma unroll
    for (int i = 0; i < 4; ++i) {
        float4* dst = reinterpret_cast<float4*>(&C[(size_t)(bm + trow * 4 + i) * D_MODEL + bn + tcol * 4]);
        *dst = make_float4(acc[i][0], acc[i][1], acc[i][2], acc[i][3]);
    }
}

__global__ __launch_bounds__(128) void gemm_qkv_kernel(
    const float* __restrict__ A,
    const float* __restrict__ Wq, const float* __restrict__ Wk,
    const float* __restrict__ Wv, int M)
{
    int gn    = blockIdx.y * TBN;           // [0,1536)
    int which = gn >> 9;                    // 0:Q 1:K 2:V
    int bn    = gn & 511;
    const float* W = (which == 0) ? Wq : (which == 1) ? Wk : Wv;
    float* C = g_QKV + (size_t)which * M * D_MODEL;
    gemm_body(A, W, C, blockIdx.x * TBM, bn, 0, D_MODEL);
}

// split-K=2: z selects K half, writes its own partial buffer (deterministic)
__global__ __launch_bounds__(128) void gemm_o_kernel(
    const float* __restrict__ Wo, int M)
{
    int z = blockIdx.z;
    float* P = g_part + (size_t)z * M * D_MODEL;
    gemm_body(g_att, Wo, P, blockIdx.x * TBM, blockIdx.y * TBN,
              z * (D_MODEL / 2), (z + 1) * (D_MODEL / 2));
}

__global__ __launch_bounds__(256) void add_kernel(float* __restrict__ out, int n4)
{
    int i = blockIdx.x * blockDim.x + threadIdx.x;
    if (i >= n4) return;
    const float4* p0 = reinterpret_cast<const float4*>(g_part);
    const float4* p1 = reinterpret_cast<const float4*>(g_part) + n4;
    float4 a = p0[i], b = p1[i];
    reinterpret_cast<float4*>(out)[i] =
        make_float4(a.x + b.x, a.y + b.y, a.z + b.z, a.w + b.w);
}

// ---------------- LSH hashes + norms ----------------
__global__ __launch_bounds__(256) void hash_kernel(const float* __restrict__ rv, int M)
{
    __shared__ float rs[HEADS * HDIM];
    for (int i = threadIdx.x; i < HEADS * HDIM; i += blockDim.x) rs[i] = rv[i];
    __syncthreads();

    int idx = blockIdx.x * blockDim.x + threadIdx.x;
    int total = 2 * M * HEADS;
    if (idx >= total) return;
    int isK = (idx >= M * HEADS) ? 1 : 0;
    int r = idx - isK * M * HEADS;
    int row = r >> 3;        // 0..M-1 (= b*1024+n)
    int h   = r & 7;

    const float4* src4 = reinterpret_cast<const float4*>(
        g_QKV + (size_t)isK * M * D_MODEL + (size_t)row * D_MODEL + h * HDIM);
    float dacc[8] = {};
    float nrm = 0.f;
#pragma unroll
    for (int c4 = 0; c4 < HDIM / 4; ++c4) {
        float4 xv = src4[c4];
        nrm += xv.x * xv.x + xv.y * xv.y + xv.z * xv.z + xv.w * xv.w;
#pragma unroll
        for (int k = 0; k < 8; ++k) {
            const float* rk = &rs[k * HDIM + c4 * 4];
            dacc[k] = fmaf(xv.x, rk[0], dacc[k]);
            dacc[k] = fmaf(xv.y, rk[1], dacc[k]);
            dacc[k] = fmaf(xv.z, rk[2], dacc[k]);
            dacc[k] = fmaf(xv.w, rk[3], dacc[k]);
        }
    }
    unsigned int bits = 0;
#pragma unroll
    for (int k = 0; k < 8; ++k) bits |= (dacc[k] >= 0.f ? 1u : 0u) << k;
    int bhn = ((row >> 10) * HEADS + h) * NSEQ + (row & (NSEQ - 1));
    if (isK) { g_kh[bhn] = (unsigned char)bits; g_kn[bhn] = nrm; }
    else     { g_qh[bhn] = (unsigned char)bits; g_qn[bhn] = nrm; }
}

// ---------------- sparse hyperbolic attention: one block per (b,h,n) ----------------
__global__ __launch_bounds__(128) void attn_kernel(int M)
{
    const int T = 128;
    const int PER = NSEQ / T;            // 8 contiguous j per thread
    int gid = blockIdx.x;                // bh*1024 + n
    int n  = gid & (NSEQ - 1);
    int bh = gid >> 10;
    int h = bh & 7, b = bh >> 3;

    const float* Q = g_QKV;
    const float* K = g_QKV + (size_t)M * D_MODEL;
    const float* V = g_QKV + 2 * (size_t)M * D_MODEL;

    __shared__ float qs[HDIM];
    __shared__ float sc[TOPK];
    __shared__ short selj[TOPK];
    __shared__ int hist[9];
    __shared__ int wsum_gt[4], wsum_eq[4];
    __shared__ int s_t, s_need;
    __shared__ float s_mx, s_sum;
    __shared__ float red[4];
    __shared__ __align__(8) float2 ored[4][HDIM / 2];

    int tid = threadIdx.x, lane = tid & 31, warp = tid >> 5;
    size_t qoff = ((size_t)(b * NSEQ + n)) * D_MODEL + h * HDIM;
    if (tid < HDIM) qs[tid] = Q[qoff + tid];
    if (tid < 9) hist[tid] = 0;
    __syncthreads();

    // --- hash match counts for my 8 contiguous keys (register-resident) ---
    unsigned int qb = g_qh[bh * NSEQ + n];
    float qn = g_qn[bh * NSEQ + n];
    const unsigned char* khb = g_kh + bh * NSEQ;
    int base = tid * PER;
    uint2 kv8 = *reinterpret_cast<const uint2*>(khb + base);
    int m[PER];
#pragma unroll
    for (int i = 0; i < PER; ++i) {
        unsigned int byte = ((i < 4 ? kv8.x >> (8 * i) : kv8.y >> (8 * (i - 4))) & 0xFFu);
        m[i] = 8 - __popc(byte ^ qb);
    }

    // --- histogram: per-thread counts, warp reduce, 1 atomic/warp/bucket ---
#pragma unroll
    for (int v = 0; v < 9; ++v) {
        int c = 0;
#pragma unroll
        for (int i = 0; i < PER; ++i) c += (m[i] == v);
        c = __reduce_add_sync(0xffffffffu, c);
        if (lane == 0 && c) atomicAdd(&hist[v], c);
    }
    __syncthreads();

    if (tid == 0) {
        int cum = 0, t = 0, need = TOPK;
        for (int v = 8; v >= 0; --v) {
            if (cum + hist[v] >= TOPK) { t = v; need = TOPK - cum; break; }
            cum += hist[v];
        }
        s_t = t; s_need = need;
    }
    __syncthreads();
    int t = s_t, need = s_need, ngt = TOPK - need;

    // --- deterministic selection positions via two shuffle scans ---
    int cgt = 0, ceq = 0;
#pragma unroll
    for (int i = 0; i < PER; ++i) { cgt += (m[i] > t); ceq += (m[i] == t); }
    int sgt = cgt, seq = ceq;
#pragma unroll
    for (int o = 1; o < 32; o <<= 1) {
        int a = __shfl_up_sync(0xffffffffu, sgt, o); if (lane >= o) sgt += a;
        int e = __shfl_up_sync(0xffffffffu, seq, o); if (lane >= o) seq += e;
    }
    if (lane == 31) { wsum_gt[warp] = sgt; wsum_eq[warp] = seq; }
    __syncthreads();
    int rgt = sgt - cgt, req = seq - ceq;
#pragma unroll
    for (int w = 0; w < 4; ++w) {
        if (w < warp) { rgt += wsum_gt[w]; req += wsum_eq[w]; }
    }
#pragma unroll
    for (int i = 0; i < PER; ++i) {
        int j = base + i;
        if (m[i] > t) selj[rgt++] = (short)j;
        else if (m[i] == t) { if (req < need) selj[ngt + req] = (short)j; req++; }
    }
    __syncthreads();

    // --- Poincare distance: dsq = qn + kn - 2 q.k (kn precomputed) ---
    if (tid < TOPK) {
        int j = selj[tid];
        const float* kr = K + ((size_t)(b * NSEQ + j)) * D_MODEL + h * HDIM;
        float kn = g_kn[bh * NSEQ + j];
        float dot = 0.f;
#pragma unroll
        for (int d0 = 0; d0 < HDIM; d0 += 4) {
            float4 kv = *reinterpret_cast<const float4*>(kr + d0);
            dot += qs[d0 + 0] * kv.x + qs[d0 + 1] * kv.y
                 + qs[d0 + 2] * kv.z + qs[d0 + 3] * kv.w;
        }
        float dsq = qn + kn - 2.f * dot;
        float denom = fmaxf((1.f - qn) * (1.f - kn), 1e-6f);
        float ca = fmaxf(1.f + 2.f * dsq / denom, 1.f);
        sc[tid] = -acoshf(ca);
    }
    __syncthreads();

    // --- softmax over TOPK scores ---
    {
        float v = (tid < TOPK) ? sc[tid] : -3.4e38f;
#pragma unroll
        for (int o = 16; o > 0; o >>= 1) v = fmaxf(v, __shfl_xor_sync(0xffffffffu, v, o));
        if (lane == 0) red[warp] = v;
        __syncthreads();
        if (tid == 0) s_mx = fmaxf(fmaxf(red[0], red[1]), fmaxf(red[2], red[3]));
        __syncthreads();
        float e = (tid < TOPK) ? expf(sc[tid] - s_mx) : 0.f;
        if (tid < TOPK) sc[tid] = e;
        float sv = e;
#pragma unroll
        for (int o = 16; o > 0; o >>= 1) sv += __shfl_xor_sync(0xffffffffu, sv, o);
        if (lane == 0) red[warp] = sv;
        __syncthreads();
        if (tid == 0) s_sum = red[0] + red[1] + red[2] + red[3];
        __syncthreads();
    }
    float inv = 1.f / s_sum;

    // --- weighted V sum: 4 warps stride the key list, float2 per lane ---
    // each warp covers a full 256B V row per key (one coalesced wavefront)
    const float* Vb = V + (size_t)b * NSEQ * D_MODEL + h * HDIM + 2 * lane;
    float2 acc = make_float2(0.f, 0.f);
    const int ITER = (TOPK + 3) / 4;     // 26
#pragma unroll
    for (int i = 0; i < ITER; ++i) {
        int s = warp + 4 * i;
        bool ok = (s < TOPK);
        int j = ok ? (int)selj[s] : 0;
        float w = ok ? sc[s] : 0.f;
        float2 v2 = *reinterpret_cast<const float2*>(Vb + (size_t)j * D_MODEL);
        acc.x = fmaf(w, v2.x, acc.x);
        acc.y = fmaf(w, v2.y, acc.y);
    }
    ored[warp][lane] = acc;
    __syncthreads();
    if (tid < HDIM / 2) {
        float2 a0 = ored[0][tid], a1 = ored[1][tid];
        float2 a2 = ored[2][tid], a3 = ored[3][tid];
        float2 r = make_float2((a0.x + a1.x + a2.x + a3.x) * inv,
                               (a0.y + a1.y + a2.y + a3.y) * inv);
        *reinterpret_cast<float2*>(
            g_att + ((size_t)(b * NSEQ + n)) * D_MODEL + h * HDIM + 2 * tid) = r;
    }
}

// ---------------- entry ----------------
extern "C" void kernel_launch(void* const* d_in, const int* in_sizes, int n_in,
                              void* d_out, int out_size)
{
    const float* x  = (const float*)d_in[0];
    const float* Wq = (const float*)d_in[1];
    const float* Wk = (const float*)d_in[2];
    const float* Wv = (const float*)d_in[3];
    const float* Wo = (const float*)d_in[4];
    const float* rv = (const float*)d_in[5];
    float* out = (float*)d_out;

    int M = in_sizes[0] / D_MODEL;   // B*N = 2048

    dim3 gq(M / TBM, (3 * D_MODEL) / TBN);    // (64, 24) = 1536 blocks
    gemm_qkv_kernel<<<gq, 128>>>(x, Wq, Wk, Wv, M);

    int hthreads = 2 * M * HEADS;             // 32768
    hash_kernel<<<(hthreads + 255) / 256, 256>>>(rv, M);

    attn_kernel<<<M * HEADS, 128>>>(M);       // 16384 blocks

    dim3 go(M / TBM, D_MODEL / TBN, 2);       // (64, 8, 2) = 1024 blocks
    gemm_o_kernel<<<go, 128>>>(Wo, M);

    int n4 = M * D_MODEL / 4;                 // 262144
    add_kernel<<<(n4 + 255) / 256, 256>>>(out, n4);
}

// round 5
// speedup vs baseline: 1.2903x; 1.1366x over previous
#include <cuda_runtime.h>
#include <math.h>

#define D_MODEL 512
#define HEADS   8
#define HDIM    64
#define NSEQ    1024
#define TOPK    102
#define MAXM    2048   // B*N for B=2

// ---------------- scratch (static device globals; no allocs) ----------------
__device__ float g_QKV[3u * MAXM * D_MODEL];   // Q | K | V, each [M,512]
__device__ float g_att[MAXM * D_MODEL];        // attention output pre-Wo
__device__ float g_part[4u * MAXM * D_MODEL];  // split-K partials for Wo GEMM
__device__ unsigned char g_qh[MAXM * HEADS];   // [(b*8+h)*1024 + n]
__device__ unsigned char g_kh[MAXM * HEADS];
__device__ float g_qn[MAXM * HEADS];           // |q|^2 per (b,h,n)
__device__ float g_kn[MAXM * HEADS];           // |k|^2 per (b,h,n)

// ---------------- SGEMM: C = A[M,512] * W[512,512]^T ----------------
// 128x64 block tile, 256 threads, 8x4 per-thread, reg-prefetch double buffer
#define GBM 128
#define GBN 64
#define GBK 16

__device__ __forceinline__ void gemm_body(
    const float* __restrict__ A, const float* __restrict__ W,
    float* __restrict__ C, int bm, int bn, int kbeg, int kend)
{
    __shared__ __align__(16) float As[GBK][GBM];   // 8 KB
    __shared__ __align__(16) float Bs[GBK][GBN];   // 4 KB

    int tid  = threadIdx.x;
    int trow = tid >> 4;          // 0..15 -> rows trow*8
    int tcol = tid & 15;          // 0..15 -> cols tcol*4
    int arow = tid >> 1;          // 0..127
    int akc  = (tid & 1) << 3;    // 0,8
    int wrow = tid >> 2;          // 0..63
    int wkc  = (tid & 3) << 2;    // 0,4,8,12

    const float* Aptr = &A[(size_t)(bm + arow) * D_MODEL + akc];
    const float* Wptr = &W[(size_t)(bn + wrow) * D_MODEL + wkc];

    float acc[8][4] = {};

    float4 a0 = *reinterpret_cast<const float4*>(Aptr + kbeg);
    float4 a1 = *reinterpret_cast<const float4*>(Aptr + kbeg + 4);
    float4 wv = *reinterpret_cast<const float4*>(Wptr + kbeg);

    for (int k0 = kbeg; k0 < kend; k0 += GBK) {
        As[akc + 0][arow] = a0.x; As[akc + 1][arow] = a0.y;
        As[akc + 2][arow] = a0.z; As[akc + 3][arow] = a0.w;
        As[akc + 4][arow] = a1.x; As[akc + 5][arow] = a1.y;
        As[akc + 6][arow] = a1.z; As[akc + 7][arow] = a1.w;
        Bs[wkc + 0][wrow] = wv.x; Bs[wkc + 1][wrow] = wv.y;
        Bs[wkc + 2][wrow] = wv.z; Bs[wkc + 3][wrow] = wv.w;
        __syncthreads();

        int kn = k0 + GBK;
        if (kn < kend) {
            a0 = *reinterpret_cast<const float4*>(Aptr + kn);
            a1 = *reinterpret_cast<const float4*>(Aptr + kn + 4);
            wv = *reinterpret_cast<const float4*>(Wptr + kn);
        }

#pragma unroll
        for (int k = 0; k < GBK; ++k) {
            float4 b4  = *reinterpret_cast<const float4*>(&Bs[k][tcol * 4]);
            float4 alo = *reinterpret_cast<const float4*>(&As[k][trow * 8]);
            float4 ahi = *reinterpret_cast<const float4*>(&As[k][trow * 8 + 4]);
            float aR[8] = {alo.x, alo.y, alo.z, alo.w, ahi.x, ahi.y, ahi.z, ahi.w};
            float bR[4] = {b4.x, b4.y, b4.z, b4.w};
#pragma unroll
            for (int i = 0; i < 8; ++i)
#pragma unroll
                for (int j = 0; j < 4; ++j)
                    acc[i][j] = fmaf(aR[i], bR[j], acc[i][j]);
        }
        __syncthreads();
    }
#pragma unroll
    for (int i = 0; i < 8; ++i) {
        float4* dst = reinterpret_cast<float4*>(
            &C[(size_t)(bm + trow * 8 + i) * D_MODEL + bn + tcol * 4]);
        *dst = make_float4(acc[i][0], acc[i][1], acc[i][2], acc[i][3]);
    }
}

__global__ __launch_bounds__(256) void gemm_qkv_kernel(
    const float* __restrict__ A,
    const float* __restrict__ Wq, const float* __restrict__ Wk,
    const float* __restrict__ Wv, int M)
{
    int gn    = blockIdx.y * GBN;           // [0,1536)
    int which = gn >> 9;                    // 0:Q 1:K 2:V
    int bn    = gn & 511;
    const float* W = (which == 0) ? Wq : (which == 1) ? Wk : Wv;
    float* C = g_QKV + (size_t)which * M * D_MODEL;
    gemm_body(A, W, C, blockIdx.x * GBM, bn, 0, D_MODEL);
}

// split-K=4: z selects K quarter, writes its own partial buffer (deterministic)
__global__ __launch_bounds__(256) void gemm_o_kernel(
    const float* __restrict__ Wo, int M)
{
    int z = blockIdx.z;
    float* P = g_part + (size_t)z * M * D_MODEL;
    gemm_body(g_att, Wo, P, blockIdx.x * GBM, blockIdx.y * GBN,
              z * (D_MODEL / 4), (z + 1) * (D_MODEL / 4));
}

__global__ __launch_bounds__(256) void add_kernel(float* __restrict__ out, int n4)
{
    int i = blockIdx.x * blockDim.x + threadIdx.x;
    if (i >= n4) return;
    const float4* p = reinterpret_cast<const float4*>(g_part);
    float4 a = p[i], b = p[i + n4], c = p[i + 2 * n4], d = p[i + 3 * n4];
    reinterpret_cast<float4*>(out)[i] =
        make_float4((a.x + b.x) + (c.x + d.x), (a.y + b.y) + (c.y + d.y),
                    (a.z + b.z) + (c.z + d.z), (a.w + b.w) + (c.w + d.w));
}

// ---------------- LSH hashes + norms ----------------
__global__ __launch_bounds__(256) void hash_kernel(const float* __restrict__ rv, int M)
{
    __shared__ float rs[HEADS * HDIM];
    for (int i = threadIdx.x; i < HEADS * HDIM; i += blockDim.x) rs[i] = rv[i];
    __syncthreads();

    int idx = blockIdx.x * blockDim.x + threadIdx.x;
    int total = 2 * M * HEADS;
    if (idx >= total) return;
    int isK = (idx >= M * HEADS) ? 1 : 0;
    int r = idx - isK * M * HEADS;
    int row = r >> 3;        // 0..M-1 (= b*1024+n)
    int h   = r & 7;

    const float4* src4 = reinterpret_cast<const float4*>(
        g_QKV + (size_t)isK * M * D_MODEL + (size_t)row * D_MODEL + h * HDIM);
    float dacc[8] = {};
    float nrm = 0.f;
#pragma unroll
    for (int c4 = 0; c4 < HDIM / 4; ++c4) {
        float4 xv = src4[c4];
        nrm += xv.x * xv.x + xv.y * xv.y + xv.z * xv.z + xv.w * xv.w;
#pragma unroll
        for (int k = 0; k < 8; ++k) {
            const float* rk = &rs[k * HDIM + c4 * 4];
            dacc[k] = fmaf(xv.x, rk[0], dacc[k]);
            dacc[k] = fmaf(xv.y, rk[1], dacc[k]);
            dacc[k] = fmaf(xv.z, rk[2], dacc[k]);
            dacc[k] = fmaf(xv.w, rk[3], dacc[k]);
        }
    }
    unsigned int bits = 0;
#pragma unroll
    for (int k = 0; k < 8; ++k) bits |= (dacc[k] >= 0.f ? 1u : 0u) << k;
    int bhn = ((row >> 10) * HEADS + h) * NSEQ + (row & (NSEQ - 1));
    if (isK) { g_kh[bhn] = (unsigned char)bits; g_kn[bhn] = nrm; }
    else     { g_qh[bhn] = (unsigned char)bits; g_qn[bhn] = nrm; }
}

// ---------------- sparse hyperbolic attention: one block per (b,h,n) ----------------
__global__ __launch_bounds__(128) void attn_kernel(int M)
{
    const int T = 128;
    const int PER = NSEQ / T;            // 8 contiguous j per thread
    int gid = blockIdx.x;                // bh*1024 + n
    int n  = gid & (NSEQ - 1);
    int bh = gid >> 10;
    int h = bh & 7, b = bh >> 3;

    const float* Q = g_QKV;
    const float* K = g_QKV + (size_t)M * D_MODEL;
    const float* V = g_QKV + 2 * (size_t)M * D_MODEL;

    __shared__ float qs[HDIM];
    __shared__ float sc[TOPK];
    __shared__ short selj[TOPK];
    __shared__ int hist[9];
    __shared__ int wsum_gt[4], wsum_eq[4];
    __shared__ int s_t, s_need;
    __shared__ float s_mx, s_sum;
    __shared__ float red[4];
    __shared__ __align__(8) float2 ored[4][HDIM / 2];

    int tid = threadIdx.x, lane = tid & 31, warp = tid >> 5;
    size_t qoff = ((size_t)(b * NSEQ + n)) * D_MODEL + h * HDIM;
    if (tid < HDIM) qs[tid] = Q[qoff + tid];
    if (tid < 9) hist[tid] = 0;
    __syncthreads();

    // --- hash match counts for my 8 contiguous keys (register-resident) ---
    unsigned int qb = g_qh[bh * NSEQ + n];
    float qn = g_qn[bh * NSEQ + n];
    const unsigned char* khb = g_kh + bh * NSEQ;
    int base = tid * PER;
    uint2 kv8 = *reinterpret_cast<const uint2*>(khb + base);
    int m[PER];
#pragma unroll
    for (int i = 0; i < PER; ++i) {
        unsigned int byte = ((i < 4 ? kv8.x >> (8 * i) : kv8.y >> (8 * (i - 4))) & 0xFFu);
        m[i] = 8 - __popc(byte ^ qb);
    }

    // --- histogram: per-thread counts, warp reduce, 1 atomic/warp/bucket ---
#pragma unroll
    for (int v = 0; v < 9; ++v) {
        int c = 0;
#pragma unroll
        for (int i = 0; i < PER; ++i) c += (m[i] == v);
        c = __reduce_add_sync(0xffffffffu, c);
        if (lane == 0 && c) atomicAdd(&hist[v], c);
    }
    __syncthreads();

    if (tid == 0) {
        int cum = 0, t = 0, need = TOPK;
        for (int v = 8; v >= 0; --v) {
            if (cum + hist[v] >= TOPK) { t = v; need = TOPK - cum; break; }
            cum += hist[v];
        }
        s_t = t; s_need = need;
    }
    __syncthreads();
    int t = s_t, need = s_need, ngt = TOPK - need;

    // --- deterministic selection positions via two shuffle scans ---
    int cgt = 0, ceq = 0;
#pragma unroll
    for (int i = 0; i < PER; ++i) { cgt += (m[i] > t); ceq += (m[i] == t); }
    int sgt = cgt, seq = ceq;
#pragma unroll
    for (int o = 1; o < 32; o <<= 1) {
        int a = __shfl_up_sync(0xffffffffu, sgt, o); if (lane >= o) sgt += a;
        int e = __shfl_up_sync(0xffffffffu, seq, o); if (lane >= o) seq += e;
    }
    if (lane == 31) { wsum_gt[warp] = sgt; wsum_eq[warp] = seq; }
    __syncthreads();
    int rgt = sgt - cgt, req = seq - ceq;
#pragma unroll
    for (int w = 0; w < 4; ++w) {
        if (w < warp) { rgt += wsum_gt[w]; req += wsum_eq[w]; }
    }
#pragma unroll
    for (int i = 0; i < PER; ++i) {
        int j = base + i;
        if (m[i] > t) selj[rgt++] = (short)j;
        else if (m[i] == t) { if (req < need) selj[ngt + req] = (short)j; req++; }
    }
    __syncthreads();

    // --- Poincare distance: dsq = qn + kn - 2 q.k (kn precomputed) ---
    if (tid < TOPK) {
        int j = selj[tid];
        const float* kr = K + ((size_t)(b * NSEQ + j)) * D_MODEL + h * HDIM;
        float kn = g_kn[bh * NSEQ + j];
        float dot = 0.f;
#pragma unroll
        for (int d0 = 0; d0 < HDIM; d0 += 4) {
            float4 kv = *reinterpret_cast<const float4*>(kr + d0);
            dot += qs[d0 + 0] * kv.x + qs[d0 + 1] * kv.y
                 + qs[d0 + 2] * kv.z + qs[d0 + 3] * kv.w;
        }
        float dsq = qn + kn - 2.f * dot;
        float denom = fmaxf((1.f - qn) * (1.f - kn), 1e-6f);
        float ca = fmaxf(1.f + 2.f * dsq / denom, 1.f);
        sc[tid] = -acoshf(ca);
    }
    __syncthreads();

    // --- softmax over TOPK scores ---
    {
        float v = (tid < TOPK) ? sc[tid] : -3.4e38f;
#pragma unroll
        for (int o = 16; o > 0; o >>= 1) v = fmaxf(v, __shfl_xor_sync(0xffffffffu, v, o));
        if (lane == 0) red[warp] = v;
        __syncthreads();
        if (tid == 0) s_mx = fmaxf(fmaxf(red[0], red[1]), fmaxf(red[2], red[3]));
        __syncthreads();
        float e = (tid < TOPK) ? expf(sc[tid] - s_mx) : 0.f;
        if (tid < TOPK) sc[tid] = e;
        float sv = e;
#pragma unroll
        for (int o = 16; o > 0; o >>= 1) sv += __shfl_xor_sync(0xffffffffu, sv, o);
        if (lane == 0) red[warp] = sv;
        __syncthreads();
        if (tid == 0) s_sum = red[0] + red[1] + red[2] + red[3];
        __syncthreads();
    }
    float inv = 1.f / s_sum;

    // --- weighted V sum: 4 warps stride the key list, float2 per lane ---
    const float* Vb = V + (size_t)b * NSEQ * D_MODEL + h * HDIM + 2 * lane;
    float2 acc = make_float2(0.f, 0.f);
    const int ITER = (TOPK + 3) / 4;     // 26
#pragma unroll
    for (int i = 0; i < ITER; ++i) {
        int s = warp + 4 * i;
        bool ok = (s < TOPK);
        int j = ok ? (int)selj[s] : 0;
        float w = ok ? sc[s] : 0.f;
        float2 v2 = *reinterpret_cast<const float2*>(Vb + (size_t)j * D_MODEL);
        acc.x = fmaf(w, v2.x, acc.x);
        acc.y = fmaf(w, v2.y, acc.y);
    }
    ored[warp][lane] = acc;
    __syncthreads();
    if (tid < HDIM / 2) {
        float2 a0 = ored[0][tid], a1 = ored[1][tid];
        float2 a2 = ored[2][tid], a3 = ored[3][tid];
        float2 r = make_float2((a0.x + a1.x + a2.x + a3.x) * inv,
                               (a0.y + a1.y + a2.y + a3.y) * inv);
        *reinterpret_cast<float2*>(
            g_att + ((size_t)(b * NSEQ + n)) * D_MODEL + h * HDIM + 2 * tid) = r;
    }
}

// ---------------- entry ----------------
extern "C" void kernel_launch(void* const* d_in, const int* in_sizes, int n_in,
                              void* d_out, int out_size)
{
    const float* x  = (const float*)d_in[0];
    const float* Wq = (const float*)d_in[1];
    const float* Wk = (const float*)d_in[2];
    const float* Wv = (const float*)d_in[3];
    const float* Wo = (const float*)d_in[4];
    const float* rv = (const float*)d_in[5];
    float* out = (float*)d_out;

    int M = in_sizes[0] / D_MODEL;   // B*N = 2048

    dim3 gq(M / GBM, (3 * D_MODEL) / GBN);    // (16, 24) = 384 blocks
    gemm_qkv_kernel<<<gq, 256>>>(x, Wq, Wk, Wv, M);

    int hthreads = 2 * M * HEADS;             // 32768
    hash_kernel<<<(hthreads + 255) / 256, 256>>>(rv, M);

    attn_kernel<<<M * HEADS, 128>>>(M);       // 16384 blocks

    dim3 go(M / GBM, D_MODEL / GBN, 4);       // (16, 8, 4) = 512 blocks
    gemm_o_kernel<<<go, 256>>>(Wo, M);

    int n4 = M * D_MODEL / 4;                 // 262144
    add_kernel<<<(n4 + 255) / 256, 256>>>(out, n4);
}

// round 6
// speedup vs baseline: 1.3609x; 1.0547x over previous
#include <cuda_runtime.h>
#include <math.h>

#define D_MODEL 512
#define HEADS   8
#define HDIM    64
#define NSEQ    1024
#define TOPK    102
#define MAXM    2048   // B*N for B=2

// ---------------- scratch (static device globals; no allocs) ----------------
__device__ float g_QKV[3u * MAXM * D_MODEL];     // Q | K | V, each [M,512]
__device__ float g_att[MAXM * D_MODEL];          // attention output pre-Wo
__device__ float g_part[4u * MAXM * D_MODEL];    // split-K partials for Wo GEMM
__device__ float g_qkvpart[2u * 3u * MAXM * D_MODEL];  // split-K partials for QKV
__device__ unsigned char g_qh[MAXM * HEADS];
__device__ unsigned char g_kh[MAXM * HEADS];
__device__ float g_qn[MAXM * HEADS];             // |q|^2 per (b,h,n)

// ---------------- SGEMM: C = A[M,512] * W[512,512]^T ----------------
// 128x64 block tile, 256 threads, 8x4 per-thread, reg-prefetch double buffer
#define GBM 128
#define GBN 64
#define GBK 16

__device__ __forceinline__ void gemm_body(
    const float* __restrict__ A, const float* __restrict__ W,
    float* __restrict__ C, int bm, int bn, int kbeg, int kend)
{
    __shared__ __align__(16) float As[GBK][GBM];   // 8 KB
    __shared__ __align__(16) float Bs[GBK][GBN];   // 4 KB

    int tid  = threadIdx.x;
    int trow = tid >> 4;          // 0..15 -> rows trow*8
    int tcol = tid & 15;          // 0..15 -> cols tcol*4
    int arow = tid >> 1;          // 0..127
    int akc  = (tid & 1) << 3;    // 0,8
    int wrow = tid >> 2;          // 0..63
    int wkc  = (tid & 3) << 2;    // 0,4,8,12

    const float* Aptr = &A[(size_t)(bm + arow) * D_MODEL + akc];
    const float* Wptr = &W[(size_t)(bn + wrow) * D_MODEL + wkc];

    float acc[8][4] = {};

    float4 a0 = *reinterpret_cast<const float4*>(Aptr + kbeg);
    float4 a1 = *reinterpret_cast<const float4*>(Aptr + kbeg + 4);
    float4 wv = *reinterpret_cast<const float4*>(Wptr + kbeg);

    for (int k0 = kbeg; k0 < kend; k0 += GBK) {
        As[akc + 0][arow] = a0.x; As[akc + 1][arow] = a0.y;
        As[akc + 2][arow] = a0.z; As[akc + 3][arow] = a0.w;
        As[akc + 4][arow] = a1.x; As[akc + 5][arow] = a1.y;
        As[akc + 6][arow] = a1.z; As[akc + 7][arow] = a1.w;
        Bs[wkc + 0][wrow] = wv.x; Bs[wkc + 1][wrow] = wv.y;
        Bs[wkc + 2][wrow] = wv.z; Bs[wkc + 3][wrow] = wv.w;
        __syncthreads();

        int kn = k0 + GBK;
        if (kn < kend) {
            a0 = *reinterpret_cast<const float4*>(Aptr + kn);
            a1 = *reinterpret_cast<const float4*>(Aptr + kn + 4);
            wv = *reinterpret_cast<const float4*>(Wptr + kn);
        }

#pragma unroll
        for (int k = 0; k < GBK; ++k) {
            float4 b4  = *reinterpret_cast<const float4*>(&Bs[k][tcol * 4]);
            float4 alo = *reinterpret_cast<const float4*>(&As[k][trow * 8]);
            float4 ahi = *reinterpret_cast<const float4*>(&As[k][trow * 8 + 4]);
            float aR[8] = {alo.x, alo.y, alo.z, alo.w, ahi.x, ahi.y, ahi.z, ahi.w};
            float bR[4] = {b4.x, b4.y, b4.z, b4.w};
#pragma unroll
            for (int i = 0; i < 8; ++i)
#pragma unroll
                for (int j = 0; j < 4; ++j)
                    acc[i][j] = fmaf(aR[i], bR[j], acc[i][j]);
        }
        __syncthreads();
    }
#pragma unroll
    for (int i = 0; i < 8; ++i) {
        float4* dst = reinterpret_cast<float4*>(
            &C[(size_t)(bm + trow * 8 + i) * D_MODEL + bn + tcol * 4]);
        *dst = make_float4(acc[i][0], acc[i][1], acc[i][2], acc[i][3]);
    }
}

// QKV with split-K=2: z picks K half, writes its own partial buffer
__global__ __launch_bounds__(256) void gemm_qkv_kernel(
    const float* __restrict__ A,
    const float* __restrict__ Wq, const float* __restrict__ Wk,
    const float* __restrict__ Wv, int M)
{
    int gn    = blockIdx.y * GBN;           // [0,1536)
    int which = gn >> 9;                    // 0:Q 1:K 2:V
    int bn    = gn & 511;
    int z     = blockIdx.z;
    const float* W = (which == 0) ? Wq : (which == 1) ? Wk : Wv;
    float* P = g_qkvpart + ((size_t)z * 3 + which) * M * D_MODEL;
    gemm_body(A, W, P, blockIdx.x * GBM, bn,
              z * (D_MODEL / 2), (z + 1) * (D_MODEL / 2));
}

__global__ __launch_bounds__(256) void add_qkv_kernel(int n4)
{
    int i = blockIdx.x * blockDim.x + threadIdx.x;
    if (i >= n4) return;
    const float4* p = reinterpret_cast<const float4*>(g_qkvpart);
    float4 a = p[i], b = p[i + n4];
    reinterpret_cast<float4*>(g_QKV)[i] =
        make_float4(a.x + b.x, a.y + b.y, a.z + b.z, a.w + b.w);
}

// Wo with split-K=4
__global__ __launch_bounds__(256) void gemm_o_kernel(
    const float* __restrict__ Wo, int M)
{
    int z = blockIdx.z;
    float* P = g_part + (size_t)z * M * D_MODEL;
    gemm_body(g_att, Wo, P, blockIdx.x * GBM, blockIdx.y * GBN,
              z * (D_MODEL / 4), (z + 1) * (D_MODEL / 4));
}

__global__ __launch_bounds__(256) void add_kernel(float* __restrict__ out, int n4)
{
    int i = blockIdx.x * blockDim.x + threadIdx.x;
    if (i >= n4) return;
    const float4* p = reinterpret_cast<const float4*>(g_part);
    float4 a = p[i], b = p[i + n4], c = p[i + 2 * n4], d = p[i + 3 * n4];
    reinterpret_cast<float4*>(out)[i] =
        make_float4((a.x + b.x) + (c.x + d.x), (a.y + b.y) + (c.y + d.y),
                    (a.z + b.z) + (c.z + d.z), (a.w + b.w) + (c.w + d.w));
}

// ---------------- LSH hashes + q norms ----------------
__global__ __launch_bounds__(256) void hash_kernel(const float* __restrict__ rv, int M)
{
    __shared__ float rs[HEADS * HDIM];
    for (int i = threadIdx.x; i < HEADS * HDIM; i += blockDim.x) rs[i] = rv[i];
    __syncthreads();

    int idx = blockIdx.x * blockDim.x + threadIdx.x;
    int total = 2 * M * HEADS;
    if (idx >= total) return;
    int isK = (idx >= M * HEADS) ? 1 : 0;
    int r = idx - isK * M * HEADS;
    int row = r >> 3;        // 0..M-1 (= b*1024+n)
    int h   = r & 7;

    const float4* src4 = reinterpret_cast<const float4*>(
        g_QKV + (size_t)isK * M * D_MODEL + (size_t)row * D_MODEL + h * HDIM);
    float dacc[8] = {};
    float nrm = 0.f;
#pragma unroll
    for (int c4 = 0; c4 < HDIM / 4; ++c4) {
        float4 xv = src4[c4];
        nrm += xv.x * xv.x + xv.y * xv.y + xv.z * xv.z + xv.w * xv.w;
#pragma unroll
        for (int k = 0; k < 8; ++k) {
            const float* rk = &rs[k * HDIM + c4 * 4];
            dacc[k] = fmaf(xv.x, rk[0], dacc[k]);
            dacc[k] = fmaf(xv.y, rk[1], dacc[k]);
            dacc[k] = fmaf(xv.z, rk[2], dacc[k]);
            dacc[k] = fmaf(xv.w, rk[3], dacc[k]);
        }
    }
    unsigned int bits = 0;
#pragma unroll
    for (int k = 0; k < 8; ++k) bits |= (dacc[k] >= 0.f ? 1u : 0u) << k;
    int bhn = ((row >> 10) * HEADS + h) * NSEQ + (row & (NSEQ - 1));
    if (isK) { g_kh[bhn] = (unsigned char)bits; }
    else     { g_qh[bhn] = (unsigned char)bits; g_qn[bhn] = nrm; }
}

// ---------------- sparse hyperbolic attention: one block per (b,h,n) ----------------
__global__ __launch_bounds__(128) void attn_kernel(int M)
{
    const int T = 128;
    const int PER = NSEQ / T;            // 8 contiguous j per thread
    int gid = blockIdx.x;                // bh*1024 + n
    int n  = gid & (NSEQ - 1);
    int bh = gid >> 10;
    int h = bh & 7, b = bh >> 3;

    const float* Q = g_QKV;
    const float* K = g_QKV + (size_t)M * D_MODEL;
    const float* V = g_QKV + 2 * (size_t)M * D_MODEL;

    __shared__ float ksm[TOPK][HDIM + 1];   // padded: bank-conflict-free
    __shared__ float qs[HDIM];
    __shared__ float sc[TOPK];
    __shared__ short selj[TOPK];
    __shared__ int hist[9];
    __shared__ int wsum_gt[4], wsum_eq[4];
    __shared__ int s_t, s_need;
    __shared__ float s_mx, s_sum;
    __shared__ float red[4];
    __shared__ __align__(8) float2 ored[4][HDIM / 2];

    int tid = threadIdx.x, lane = tid & 31, warp = tid >> 5;
    size_t qoff = ((size_t)(b * NSEQ + n)) * D_MODEL + h * HDIM;
    if (tid < HDIM) qs[tid] = Q[qoff + tid];
    if (tid < 9) hist[tid] = 0;
    __syncthreads();

    // --- hash match counts for my 8 contiguous keys ---
    unsigned int qb = g_qh[bh * NSEQ + n];
    float qn = g_qn[bh * NSEQ + n];
    const unsigned char* khb = g_kh + bh * NSEQ;
    int base = tid * PER;
    uint2 kv8 = *reinterpret_cast<const uint2*>(khb + base);
    int m[PER];
#pragma unroll
    for (int i = 0; i < PER; ++i) {
        unsigned int byte = ((i < 4 ? kv8.x >> (8 * i) : kv8.y >> (8 * (i - 4))) & 0xFFu);
        m[i] = 8 - __popc(byte ^ qb);
    }

    // --- histogram ---
#pragma unroll
    for (int v = 0; v < 9; ++v) {
        int c = 0;
#pragma unroll
        for (int i = 0; i < PER; ++i) c += (m[i] == v);
        c = __reduce_add_sync(0xffffffffu, c);
        if (lane == 0 && c) atomicAdd(&hist[v], c);
    }
    __syncthreads();

    if (tid == 0) {
        int cum = 0, t = 0, need = TOPK;
        for (int v = 8; v >= 0; --v) {
            if (cum + hist[v] >= TOPK) { t = v; need = TOPK - cum; break; }
            cum += hist[v];
        }
        s_t = t; s_need = need;
    }
    __syncthreads();
    int t = s_t, need = s_need, ngt = TOPK - need;

    // --- deterministic selection via two shuffle scans ---
    int cgt = 0, ceq = 0;
#pragma unroll
    for (int i = 0; i < PER; ++i) { cgt += (m[i] > t); ceq += (m[i] == t); }
    int sgt = cgt, seq = ceq;
#pragma unroll
    for (int o = 1; o < 32; o <<= 1) {
        int a = __shfl_up_sync(0xffffffffu, sgt, o); if (lane >= o) sgt += a;
        int e = __shfl_up_sync(0xffffffffu, seq, o); if (lane >= o) seq += e;
    }
    if (lane == 31) { wsum_gt[warp] = sgt; wsum_eq[warp] = seq; }
    __syncthreads();
    int rgt = sgt - cgt, req = seq - ceq;
#pragma unroll
    for (int w = 0; w < 4; ++w) {
        if (w < warp) { rgt += wsum_gt[w]; req += wsum_eq[w]; }
    }
#pragma unroll
    for (int i = 0; i < PER; ++i) {
        int j = base + i;
        if (m[i] > t) selj[rgt++] = (short)j;
        else if (m[i] == t) { if (req < need) selj[ngt + req] = (short)j; req++; }
    }
    __syncthreads();

    // --- stage selected K rows into padded smem (coalesced) ---
    const float* Kb = K + (size_t)b * NSEQ * D_MODEL + h * HDIM;
    for (int idx = tid; idx < TOPK * 16; idx += T) {
        int s  = idx >> 4;
        int c4 = (idx & 15) << 2;
        int j  = selj[s];
        float4 kv = *reinterpret_cast<const float4*>(Kb + (size_t)j * D_MODEL + c4);
        ksm[s][c4 + 0] = kv.x; ksm[s][c4 + 1] = kv.y;
        ksm[s][c4 + 2] = kv.z; ksm[s][c4 + 3] = kv.w;
    }
    __syncthreads();

    // --- Poincare distance from smem: dsq = qn + kn - 2 q.k ---
    if (tid < TOPK) {
        const float* kr = ksm[tid];
        float dot = 0.f, kn = 0.f;
#pragma unroll
        for (int d0 = 0; d0 < HDIM; ++d0) {
            float kvv = kr[d0];
            dot = fmaf(qs[d0], kvv, dot);
            kn  = fmaf(kvv, kvv, kn);
        }
        float dsq = qn + kn - 2.f * dot;
        float denom = fmaxf((1.f - qn) * (1.f - kn), 1e-6f);
        float ca = fmaxf(1.f + 2.f * dsq / denom, 1.f);
        sc[tid] = -acoshf(ca);
    }
    __syncthreads();

    // --- softmax over TOPK scores ---
    {
        float v = (tid < TOPK) ? sc[tid] : -3.4e38f;
#pragma unroll
        for (int o = 16; o > 0; o >>= 1) v = fmaxf(v, __shfl_xor_sync(0xffffffffu, v, o));
        if (lane == 0) red[warp] = v;
        __syncthreads();
        if (tid == 0) s_mx = fmaxf(fmaxf(red[0], red[1]), fmaxf(red[2], red[3]));
        __syncthreads();
        float e = (tid < TOPK) ? expf(sc[tid] - s_mx) : 0.f;
        if (tid < TOPK) sc[tid] = e;
        float sv = e;
#pragma unroll
        for (int o = 16; o > 0; o >>= 1) sv += __shfl_xor_sync(0xffffffffu, sv, o);
        if (lane == 0) red[warp] = sv;
        __syncthreads();
        if (tid == 0) s_sum = red[0] + red[1] + red[2] + red[3];
        __syncthreads();
    }
    float inv = 1.f / s_sum;

    // --- weighted V sum: 4 warps stride the key list, float2 per lane ---
    const float* Vb = V + (size_t)b * NSEQ * D_MODEL + h * HDIM + 2 * lane;
    float2 acc = make_float2(0.f, 0.f);
    const int ITER = (TOPK + 3) / 4;     // 26
#pragma unroll
    for (int i = 0; i < ITER; ++i) {
        int s = warp + 4 * i;
        bool ok = (s < TOPK);
        int j = ok ? (int)selj[s] : 0;
        float w = ok ? sc[s] : 0.f;
        float2 v2 = *reinterpret_cast<const float2*>(Vb + (size_t)j * D_MODEL);
        acc.x = fmaf(w, v2.x, acc.x);
        acc.y = fmaf(w, v2.y, acc.y);
    }
    ored[warp][lane] = acc;
    __syncthreads();
    if (tid < HDIM / 2) {
        float2 a0 = ored[0][tid], a1 = ored[1][tid];
        float2 a2 = ored[2][tid], a3 = ored[3][tid];
        float2 r = make_float2((a0.x + a1.x + a2.x + a3.x) * inv,
                               (a0.y + a1.y + a2.y + a3.y) * inv);
        *reinterpret_cast<float2*>(
            g_att + ((size_t)(b * NSEQ + n)) * D_MODEL + h * HDIM + 2 * tid) = r;
    }
}

// ---------------- entry ----------------
extern "C" void kernel_launch(void* const* d_in, const int* in_sizes, int n_in,
                              void* d_out, int out_size)
{
    const float* x  = (const float*)d_in[0];
    const float* Wq = (const float*)d_in[1];
    const float* Wk = (const float*)d_in[2];
    const float* Wv = (const float*)d_in[3];
    const float* Wo = (const float*)d_in[4];
    const float* rv = (const float*)d_in[5];
    float* out = (float*)d_out;

    int M = in_sizes[0] / D_MODEL;   // B*N = 2048

    dim3 gq(M / GBM, (3 * D_MODEL) / GBN, 2); // (16, 24, 2) = 768 blocks
    gemm_qkv_kernel<<<gq, 256>>>(x, Wq, Wk, Wv, M);

    int nq4 = 3 * M * D_MODEL / 4;            // 786432
    add_qkv_kernel<<<(nq4 + 255) / 256, 256>>>(nq4);

    int hthreads = 2 * M * HEADS;             // 32768
    hash_kernel<<<(hthreads + 255) / 256, 256>>>(rv, M);

    attn_kernel<<<M * HEADS, 128>>>(M);       // 16384 blocks

    dim3 go(M / GBM, D_MODEL / GBN, 4);       // (16, 8, 4) = 512 blocks
    gemm_o_kernel<<<go, 256>>>(Wo, M);

    int n4 = M * D_MODEL / 4;                 // 262144
    add_kernel<<<(n4 + 255) / 256, 256>>>(out, n4);
}

// round 7
// speedup vs baseline: 1.4032x; 1.0311x over previous
#include <cuda_runtime.h>
#include <math.h>

#define D_MODEL 512
#define HEADS   8
#define HDIM    64
#define NSEQ    1024
#define TOPK    102
#define MAXM    2048   // B*N for B=2

// ---------------- scratch (static device globals; no allocs) ----------------
__device__ float g_QKV[3u * MAXM * D_MODEL];     // Q | K | V, each [M,512]
__device__ float g_att[MAXM * D_MODEL];          // attention output pre-Wo
__device__ float g_part[4u * MAXM * D_MODEL];    // split-K partials for Wo GEMM
__device__ float g_qkvpart[2u * 3u * MAXM * D_MODEL];  // split-K partials for QKV
__device__ unsigned char g_qh[MAXM * HEADS];
__device__ unsigned char g_kh[MAXM * HEADS];
__device__ float g_qn[MAXM * HEADS];             // |q|^2 per (b,h,n)

// ---------------- SGEMM: C = A[M,512] * W[512,512]^T ----------------
#define GBM 128
#define GBN 64
#define GBK 16

__device__ __forceinline__ void gemm_body(
    const float* __restrict__ A, const float* __restrict__ W,
    float* __restrict__ C, int bm, int bn, int kbeg, int kend)
{
    __shared__ __align__(16) float As[GBK][GBM];   // 8 KB
    __shared__ __align__(16) float Bs[GBK][GBN];   // 4 KB

    int tid  = threadIdx.x;
    int trow = tid >> 4;          // 0..15 -> rows trow*8
    int tcol = tid & 15;          // 0..15 -> cols tcol*4
    int arow = tid >> 1;          // 0..127
    int akc  = (tid & 1) << 3;    // 0,8
    int wrow = tid >> 2;          // 0..63
    int wkc  = (tid & 3) << 2;    // 0,4,8,12

    const float* Aptr = &A[(size_t)(bm + arow) * D_MODEL + akc];
    const float* Wptr = &W[(size_t)(bn + wrow) * D_MODEL + wkc];

    float acc[8][4] = {};

    float4 a0 = *reinterpret_cast<const float4*>(Aptr + kbeg);
    float4 a1 = *reinterpret_cast<const float4*>(Aptr + kbeg + 4);
    float4 wv = *reinterpret_cast<const float4*>(Wptr + kbeg);

    for (int k0 = kbeg; k0 < kend; k0 += GBK) {
        As[akc + 0][arow] = a0.x; As[akc + 1][arow] = a0.y;
        As[akc + 2][arow] = a0.z; As[akc + 3][arow] = a0.w;
        As[akc + 4][arow] = a1.x; As[akc + 5][arow] = a1.y;
        As[akc + 6][arow] = a1.z; As[akc + 7][arow] = a1.w;
        Bs[wkc + 0][wrow] = wv.x; Bs[wkc + 1][wrow] = wv.y;
        Bs[wkc + 2][wrow] = wv.z; Bs[wkc + 3][wrow] = wv.w;
        __syncthreads();

        int kn = k0 + GBK;
        if (kn < kend) {
            a0 = *reinterpret_cast<const float4*>(Aptr + kn);
            a1 = *reinterpret_cast<const float4*>(Aptr + kn + 4);
            wv = *reinterpret_cast<const float4*>(Wptr + kn);
        }

#pragma unroll
        for (int k = 0; k < GBK; ++k) {
            float4 b4  = *reinterpret_cast<const float4*>(&Bs[k][tcol * 4]);
            float4 alo = *reinterpret_cast<const float4*>(&As[k][trow * 8]);
            float4 ahi = *reinterpret_cast<const float4*>(&As[k][trow * 8 + 4]);
            float aR[8] = {alo.x, alo.y, alo.z, alo.w, ahi.x, ahi.y, ahi.z, ahi.w};
            float bR[4] = {b4.x, b4.y, b4.z, b4.w};
#pragma unroll
            for (int i = 0; i < 8; ++i)
#pragma unroll
                for (int j = 0; j < 4; ++j)
                    acc[i][j] = fmaf(aR[i], bR[j], acc[i][j]);
        }
        __syncthreads();
    }
#pragma unroll
    for (int i = 0; i < 8; ++i) {
        float4* dst = reinterpret_cast<float4*>(
            &C[(size_t)(bm + trow * 8 + i) * D_MODEL + bn + tcol * 4]);
        *dst = make_float4(acc[i][0], acc[i][1], acc[i][2], acc[i][3]);
    }
}

__global__ __launch_bounds__(256) void gemm_qkv_kernel(
    const float* __restrict__ A,
    const float* __restrict__ Wq, const float* __restrict__ Wk,
    const float* __restrict__ Wv, int M)
{
    int gn    = blockIdx.y * GBN;
    int which = gn >> 9;
    int bn    = gn & 511;
    int z     = blockIdx.z;
    const float* W = (which == 0) ? Wq : (which == 1) ? Wk : Wv;
    float* P = g_qkvpart + ((size_t)z * 3 + which) * M * D_MODEL;
    gemm_body(A, W, P, blockIdx.x * GBM, bn,
              z * (D_MODEL / 2), (z + 1) * (D_MODEL / 2));
}

__global__ __launch_bounds__(256) void add_qkv_kernel(int n4)
{
    int i = blockIdx.x * blockDim.x + threadIdx.x;
    if (i >= n4) return;
    const float4* p = reinterpret_cast<const float4*>(g_qkvpart);
    float4 a = p[i], b = p[i + n4];
    reinterpret_cast<float4*>(g_QKV)[i] =
        make_float4(a.x + b.x, a.y + b.y, a.z + b.z, a.w + b.w);
}

__global__ __launch_bounds__(256) void gemm_o_kernel(
    const float* __restrict__ Wo, int M)
{
    int z = blockIdx.z;
    float* P = g_part + (size_t)z * M * D_MODEL;
    gemm_body(g_att, Wo, P, blockIdx.x * GBM, blockIdx.y * GBN,
              z * (D_MODEL / 4), (z + 1) * (D_MODEL / 4));
}

__global__ __launch_bounds__(256) void add_kernel(float* __restrict__ out, int n4)
{
    int i = blockIdx.x * blockDim.x + threadIdx.x;
    if (i >= n4) return;
    const float4* p = reinterpret_cast<const float4*>(g_part);
    float4 a = p[i], b = p[i + n4], c = p[i + 2 * n4], d = p[i + 3 * n4];
    reinterpret_cast<float4*>(out)[i] =
        make_float4((a.x + b.x) + (c.x + d.x), (a.y + b.y) + (c.y + d.y),
                    (a.z + b.z) + (c.z + d.z), (a.w + b.w) + (c.w + d.w));
}

// ---------------- LSH hashes + q norms ----------------
__global__ __launch_bounds__(256) void hash_kernel(const float* __restrict__ rv, int M)
{
    __shared__ float rs[HEADS * HDIM];
    for (int i = threadIdx.x; i < HEADS * HDIM; i += blockDim.x) rs[i] = rv[i];
    __syncthreads();

    int idx = blockIdx.x * blockDim.x + threadIdx.x;
    int total = 2 * M * HEADS;
    if (idx >= total) return;
    int isK = (idx >= M * HEADS) ? 1 : 0;
    int r = idx - isK * M * HEADS;
    int row = r >> 3;
    int h   = r & 7;

    const float4* src4 = reinterpret_cast<const float4*>(
        g_QKV + (size_t)isK * M * D_MODEL + (size_t)row * D_MODEL + h * HDIM);
    float dacc[8] = {};
    float nrm = 0.f;
#pragma unroll
    for (int c4 = 0; c4 < HDIM / 4; ++c4) {
        float4 xv = src4[c4];
        nrm += xv.x * xv.x + xv.y * xv.y + xv.z * xv.z + xv.w * xv.w;
#pragma unroll
        for (int k = 0; k < 8; ++k) {
            const float* rk = &rs[k * HDIM + c4 * 4];
            dacc[k] = fmaf(xv.x, rk[0], dacc[k]);
            dacc[k] = fmaf(xv.y, rk[1], dacc[k]);
            dacc[k] = fmaf(xv.z, rk[2], dacc[k]);
            dacc[k] = fmaf(xv.w, rk[3], dacc[k]);
        }
    }
    unsigned int bits = 0;
#pragma unroll
    for (int k = 0; k < 8; ++k) bits |= (dacc[k] >= 0.f ? 1u : 0u) << k;
    int bhn = ((row >> 10) * HEADS + h) * NSEQ + (row & (NSEQ - 1));
    if (isK) { g_kh[bhn] = (unsigned char)bits; }
    else     { g_qh[bhn] = (unsigned char)bits; g_qn[bhn] = nrm; }
}

// ---------------- sparse hyperbolic attention: one block per (b,h,n) ----------------
__global__ __launch_bounds__(128) void attn_kernel(int M)
{
    const int T = 128;
    const int PER = NSEQ / T;            // 8 contiguous j per thread
    int gid = blockIdx.x;
    int n  = gid & (NSEQ - 1);
    int bh = gid >> 10;
    int h = bh & 7, b = bh >> 3;

    const float* Q = g_QKV;
    const float* K = g_QKV + (size_t)M * D_MODEL;
    const float* V = g_QKV + 2 * (size_t)M * D_MODEL;

    __shared__ float ksm[TOPK][HDIM + 1];   // padded: bank-conflict-free
    __shared__ float qs[HDIM];
    __shared__ float sc[TOPK];
    __shared__ short selj[TOPK];
    __shared__ int whist[4][9];
    __shared__ int wsum_gt[4], wsum_eq[4];
    __shared__ float s_sum;
    __shared__ __align__(8) float2 ored[4][HDIM / 2];

    int tid = threadIdx.x, lane = tid & 31, warp = tid >> 5;
    size_t qoff = ((size_t)(b * NSEQ + n)) * D_MODEL + h * HDIM;
    if (tid < HDIM) qs[tid] = Q[qoff + tid];

    // --- hash match counts for my 8 contiguous keys ---
    unsigned int qb = g_qh[bh * NSEQ + n];
    float qn = g_qn[bh * NSEQ + n];
    const unsigned char* khb = g_kh + bh * NSEQ;
    int base = tid * PER;
    uint2 kv8 = *reinterpret_cast<const uint2*>(khb + base);
    int m[PER];
#pragma unroll
    for (int i = 0; i < PER; ++i) {
        unsigned int byte = ((i < 4 ? kv8.x >> (8 * i) : kv8.y >> (8 * (i - 4))) & 0xFFu);
        m[i] = 8 - __popc(byte ^ qb);
    }

    // --- per-warp histogram via redux; no atomics ---
#pragma unroll
    for (int v = 0; v < 9; ++v) {
        int c = 0;
#pragma unroll
        for (int i = 0; i < PER; ++i) c += (m[i] == v);
        c = __reduce_add_sync(0xffffffffu, c);
        if (lane == v) whist[warp][v] = c;   // lane v holds bucket v's sum
    }
    __syncthreads();   // (1) qs + whist ready

    // --- every thread computes threshold in registers (uniform) ---
    int t = 0, need = TOPK;
    {
        int cum = 0;
#pragma unroll
        for (int v = 8; v >= 0; --v) {
            int hv = whist[0][v] + whist[1][v] + whist[2][v] + whist[3][v];
            int ncum = cum + hv;
            if (cum < TOPK && ncum >= TOPK) { t = v; need = TOPK - cum; }
            cum = ncum;
        }
    }
    int ngt = TOPK - need;

    // --- deterministic selection positions via two shuffle scans ---
    int cgt = 0, ceq = 0;
#pragma unroll
    for (int i = 0; i < PER; ++i) { cgt += (m[i] > t); ceq += (m[i] == t); }
    int sgt = cgt, seq = ceq;
#pragma unroll
    for (int o = 1; o < 32; o <<= 1) {
        int a = __shfl_up_sync(0xffffffffu, sgt, o); if (lane >= o) sgt += a;
        int e = __shfl_up_sync(0xffffffffu, seq, o); if (lane >= o) seq += e;
    }
    if (lane == 31) { wsum_gt[warp] = sgt; wsum_eq[warp] = seq; }
    __syncthreads();   // (2) wsum ready
    int rgt = sgt - cgt, req = seq - ceq;
#pragma unroll
    for (int w = 0; w < 4; ++w) {
        if (w < warp) { rgt += wsum_gt[w]; req += wsum_eq[w]; }
    }
#pragma unroll
    for (int i = 0; i < PER; ++i) {
        int j = base + i;
        if (m[i] > t) selj[rgt++] = (short)j;
        else if (m[i] == t) { if (req < need) selj[ngt + req] = (short)j; req++; }
    }
    __syncthreads();   // (3) selj ready

    // --- stage selected K rows into padded smem (coalesced) ---
    const float* Kb = K + (size_t)b * NSEQ * D_MODEL + h * HDIM;
    for (int idx = tid; idx < TOPK * 16; idx += T) {
        int s  = idx >> 4;
        int c4 = (idx & 15) << 2;
        int j  = selj[s];
        float4 kv = *reinterpret_cast<const float4*>(Kb + (size_t)j * D_MODEL + c4);
        ksm[s][c4 + 0] = kv.x; ksm[s][c4 + 1] = kv.y;
        ksm[s][c4 + 2] = kv.z; ksm[s][c4 + 3] = kv.w;
    }
    __syncthreads();   // (4) ksm ready

    // --- Poincare distance from smem, 4 accumulator chains ---
    if (tid < TOPK) {
        const float* kr = ksm[tid];
        float d0 = 0.f, d1 = 0.f, d2 = 0.f, d3 = 0.f;
        float n0 = 0.f, n1 = 0.f, n2 = 0.f, n3 = 0.f;
#pragma unroll
        for (int c = 0; c < HDIM; c += 4) {
            float k0 = kr[c], k1 = kr[c + 1], k2 = kr[c + 2], k3 = kr[c + 3];
            d0 = fmaf(qs[c + 0], k0, d0); n0 = fmaf(k0, k0, n0);
            d1 = fmaf(qs[c + 1], k1, d1); n1 = fmaf(k1, k1, n1);
            d2 = fmaf(qs[c + 2], k2, d2); n2 = fmaf(k2, k2, n2);
            d3 = fmaf(qs[c + 3], k3, d3); n3 = fmaf(k3, k3, n3);
        }
        float dot = (d0 + d1) + (d2 + d3);
        float kn  = (n0 + n1) + (n2 + n3);
        float dsq = qn + kn - 2.f * dot;
        float denom = fmaxf((1.f - qn) * (1.f - kn), 1e-6f);
        float ca = fmaxf(1.f + 2.f * dsq / denom, 1.f);
        sc[tid] = -acoshf(ca);
    }
    __syncthreads();   // (5) sc ready

    // --- softmax entirely inside warp 0 ---
    if (warp == 0) {
        float v0 = sc[lane];
        float v1 = sc[lane + 32];
        float v2 = sc[lane + 64];
        float v3 = (lane + 96 < TOPK) ? sc[lane + 96] : -3.4e38f;
        float mx = fmaxf(fmaxf(v0, v1), fmaxf(v2, v3));
#pragma unroll
        for (int o = 16; o > 0; o >>= 1) mx = fmaxf(mx, __shfl_xor_sync(0xffffffffu, mx, o));
        float e0 = expf(v0 - mx), e1 = expf(v1 - mx), e2 = expf(v2 - mx);
        float e3 = (lane + 96 < TOPK) ? expf(v3 - mx) : 0.f;
        sc[lane] = e0; sc[lane + 32] = e1; sc[lane + 64] = e2;
        if (lane + 96 < TOPK) sc[lane + 96] = e3;
        float sv = (e0 + e1) + (e2 + e3);
#pragma unroll
        for (int o = 16; o > 0; o >>= 1) sv += __shfl_xor_sync(0xffffffffu, sv, o);
        if (lane == 0) s_sum = sv;
    }
    __syncthreads();   // (6) exp + sum ready
    float inv = 1.f / s_sum;

    // --- weighted V sum: 4 warps stride the key list, float2 per lane ---
    const float* Vb = V + (size_t)b * NSEQ * D_MODEL + h * HDIM + 2 * lane;
    float2 acc = make_float2(0.f, 0.f);
    const int ITER = (TOPK + 3) / 4;     // 26
#pragma unroll
    for (int i = 0; i < ITER; ++i) {
        int s = warp + 4 * i;
        bool ok = (s < TOPK);
        int j = ok ? (int)selj[s] : 0;
        float w = ok ? sc[s] : 0.f;
        float2 v2 = *reinterpret_cast<const float2*>(Vb + (size_t)j * D_MODEL);
        acc.x = fmaf(w, v2.x, acc.x);
        acc.y = fmaf(w, v2.y, acc.y);
    }
    ored[warp][lane] = acc;
    __syncthreads();   // (7)
    if (tid < HDIM / 2) {
        float2 a0 = ored[0][tid], a1 = ored[1][tid];
        float2 a2 = ored[2][tid], a3 = ored[3][tid];
        float2 r = make_float2((a0.x + a1.x + a2.x + a3.x) * inv,
                               (a0.y + a1.y + a2.y + a3.y) * inv);
        *reinterpret_cast<float2*>(
            g_att + ((size_t)(b * NSEQ + n)) * D_MODEL + h * HDIM + 2 * tid) = r;
    }
}

// ---------------- entry ----------------
extern "C" void kernel_launch(void* const* d_in, const int* in_sizes, int n_in,
                              void* d_out, int out_size)
{
    const float* x  = (const float*)d_in[0];
    const float* Wq = (const float*)d_in[1];
    const float* Wk = (const float*)d_in[2];
    const float* Wv = (const float*)d_in[3];
    const float* Wo = (const float*)d_in[4];
    const float* rv = (const float*)d_in[5];
    float* out = (float*)d_out;

    int M = in_sizes[0] / D_MODEL;   // B*N = 2048

    dim3 gq(M / GBM, (3 * D_MODEL) / GBN, 2); // (16, 24, 2) = 768 blocks
    gemm_qkv_kernel<<<gq, 256>>>(x, Wq, Wk, Wv, M);

    int nq4 = 3 * M * D_MODEL / 4;
    add_qkv_kernel<<<(nq4 + 255) / 256, 256>>>(nq4);

    int hthreads = 2 * M * HEADS;
    hash_kernel<<<(hthreads + 255) / 256, 256>>>(rv, M);

    attn_kernel<<<M * HEADS, 128>>>(M);       // 16384 blocks

    dim3 go(M / GBM, D_MODEL / GBN, 4);       // (16, 8, 4) = 512 blocks
    gemm_o_kernel<<<go, 256>>>(Wo, M);

    int n4 = M * D_MODEL / 4;
    add_kernel<<<(n4 + 255) / 256, 256>>>(out, n4);
}